// round 14
// baseline (speedup 1.0000x reference)
#include <cuda_runtime.h>

#define TT 100
#define BB 16384

// Interleaved weights: [k][j][role] -> the 4 roles of a warp hit 4 CONSECUTIVE
// float4s inside one 64B LDS.128 window -> conflict-free broadcast.
struct Smem {
    float4 ecI[2][2][4];
    float4 erI[2][2][4];
    float4 sI [6][4][4];
    float4 chI[4][6][4];
    float4 rhI[4][6][4];
    float4 tI [4][4];      // roles 0-2 -> Wco rows, role 3 -> Wro
    float  bec[8], ber[8], bs[24], bch[16], bco[3], brh[16], bro[1];
};

// bit i of m -> exact 0.0f / 1.0f (3 ALU ops)
__device__ __forceinline__ float bit2f(unsigned m, int i) {
    return __int_as_float((((int)(m << (31 - i))) >> 31) & 0x3F800000);
}

// snntorch Leaky, reset='subtract', THR=1, BETA=0.9 — bit-exact vs reference.
__device__ __forceinline__ float lif(float cur, float& m, unsigned& mask, unsigned bit) {
    float mold = m;
    m = fmaf(0.9f, m, cur);
    if (mold > 1.0f) m -= 1.0f;
    bool sp = (m > 1.0f);
    if (sp) mask |= bit;
    return sp ? 1.0f : 0.0f;
}
__device__ __forceinline__ void lif_nom(float cur, float& m) {
    float mold = m;
    m = fmaf(0.9f, m, cur);
    if (mold > 1.0f) m -= 1.0f;
}

__device__ __forceinline__ unsigned merge4(unsigned m) {
    m |= __shfl_xor_sync(0xFFFFFFFFu, m, 8);
    m |= __shfl_xor_sync(0xFFFFFFFFu, m, 16);
    return m;
}

__global__ void __launch_bounds__(256)
snn_kernel(const float* __restrict__ x,
           const float* __restrict__ We_c, const float* __restrict__ be_c,
           const float* __restrict__ We_r, const float* __restrict__ be_r,
           const float* __restrict__ Wsp,  const float* __restrict__ bsp,
           const float* __restrict__ Wchp, const float* __restrict__ bchp,
           const float* __restrict__ Wcop, const float* __restrict__ bcop,
           const float* __restrict__ Wrhp, const float* __restrict__ brhp,
           const float* __restrict__ Wrop, const float* __restrict__ brop,
           float* __restrict__ out)
{
    __shared__ __align__(16) Smem sm;
    const int tid = threadIdx.x;

    // ---- staging: permute weights into interleaved layout ----
    for (int idx = tid; idx < 64; idx += 256) {          // ecI / erI
        int c = idx & 3, role = (idx >> 2) & 3, j = (idx >> 4) & 1, k = idx >> 5;
        int col = 4 * j + c, row = 2 * role + k;
        ((float*)sm.ecI)[idx] = (col < 6) ? We_c[row * 6 + col] : 0.f;
        ((float*)sm.erI)[idx] = (col < 6) ? We_r[row * 6 + col] : 0.f;
    }
    for (int idx = tid; idx < 384; idx += 256) {         // sI
        int c = idx & 3, role = (idx >> 2) & 3, j = (idx >> 4) & 3, k = idx >> 6;
        ((float*)sm.sI)[idx] = Wsp[(6 * role + k) * 16 + 4 * j + c];
    }
    for (int idx = tid; idx < 384; idx += 256) {         // chI / rhI
        int c = idx & 3, role = (idx >> 2) & 3, jk = idx >> 4;
        int j = jk % 6, k = jk / 6, off = (4 * role + k) * 24 + 4 * j + c;
        ((float*)sm.chI)[idx] = Wchp[off];
        ((float*)sm.rhI)[idx] = Wrhp[off];
    }
    for (int idx = tid; idx < 64; idx += 256) {          // tI
        int c = idx & 3, role = (idx >> 2) & 3, j = idx >> 4;
        ((float*)sm.tI)[idx] = (role < 3) ? Wcop[role * 16 + 4 * j + c]
                                          : Wrop[4 * j + c];
    }
    if (tid < 8)  { sm.bec[tid] = be_c[tid]; sm.ber[tid] = be_r[tid]; }
    if (tid < 24) sm.bs[tid]  = bsp[tid];
    if (tid < 16) { sm.bch[tid] = bchp[tid]; sm.brh[tid] = brhp[tid]; }
    if (tid < 3)  sm.bco[tid] = bcop[tid];
    if (tid == 0) sm.bro[0] = brop[0];
    __syncthreads();

    // ---- 4-way role split, 2 elements per thread ----
    const int lane = tid & 31;
    const int warp = tid >> 5;           // 0..7
    const int role = lane >> 3;          // 0..3
    const int sub  = lane & 7;
    const int eA   = blockIdx.x * 128 + warp * 16 + sub;

    const int eo = role * 2;
    const int so = role * 6;
    const int ho = role * 4;

    // biases -> registers
    float b_ec[2], b_er[2], b_sh[6], b_ch[4], b_rh[4];
#pragma unroll
    for (int k = 0; k < 2; ++k) { b_ec[k] = sm.bec[eo + k]; b_er[k] = sm.ber[eo + k]; }
#pragma unroll
    for (int k = 0; k < 6; ++k) b_sh[k] = sm.bs[so + k];
#pragma unroll
    for (int k = 0; k < 4; ++k) { b_ch[k] = sm.bch[ho + k]; b_rh[k] = sm.brh[ho + k]; }
    const float btail = (role < 3) ? sm.bco[role] : sm.bro[0];
    const bool  isco  = (role < 3);

    // membranes, per element
    float m_ec[2][2], m_er[2][2], m_sh[2][6], m_ch[2][4], m_rh[2][4], m_tail[2];
#pragma unroll
    for (int u = 0; u < 2; ++u) {
#pragma unroll
        for (int i = 0; i < 2; ++i) { m_ec[u][i] = 0.f; m_er[u][i] = 0.f; }
#pragma unroll
        for (int i = 0; i < 6; ++i) m_sh[u][i] = 0.f;
#pragma unroll
        for (int i = 0; i < 4; ++i) { m_ch[u][i] = 0.f; m_rh[u][i] = 0.f; }
        m_tail[u] = 0.f;
    }

    const size_t TB = (size_t)TT * BB;
    float* const p_mco = out;
    float* const p_sch = out + TB * 3;
    float* const p_mro = out + TB * 19;
    float* const p_srh = out + TB * 20;
    float* const p_ssh = out + TB * 36;
    float* const p_sec = out + TB * 60;
    float* const p_ser = out + TB * 68;

#pragma unroll 1
    for (int t = 0; t < TT; ++t) {
        const size_t rA = (size_t)t * BB + eA;

        float xv[2][8];
#pragma unroll
        for (int u = 0; u < 2; ++u) {
            const float2* xp = (const float2*)(x + (rA + (u ? 8 : 0)) * 6);
            const float2 a0 = xp[0], a1 = xp[1], a2 = xp[2];
            xv[u][0] = a0.x; xv[u][1] = a0.y; xv[u][2] = a1.x; xv[u][3] = a1.y;
            xv[u][4] = a2.x; xv[u][5] = a2.y; xv[u][6] = 0.f;  xv[u][7] = 0.f;
        }

        // ---- encoders (weights loaded once, both elements) ----
        float s_ec[2][2], s_er[2][2];
        unsigned em[2] = {0u, 0u};
#pragma unroll
        for (int k = 0; k < 2; ++k) {
            float accA = 0.f, accB = 0.f;
#pragma unroll
            for (int j = 0; j < 2; ++j) {
                const float4 w = sm.ecI[k][j][role];
                accA = fmaf(xv[0][4*j+0], w.x, accA); accB = fmaf(xv[1][4*j+0], w.x, accB);
                accA = fmaf(xv[0][4*j+1], w.y, accA); accB = fmaf(xv[1][4*j+1], w.y, accB);
                accA = fmaf(xv[0][4*j+2], w.z, accA); accB = fmaf(xv[1][4*j+2], w.z, accB);
                accA = fmaf(xv[0][4*j+3], w.w, accA); accB = fmaf(xv[1][4*j+3], w.w, accB);
            }
            s_ec[0][k] = lif(accA + b_ec[k], m_ec[0][k], em[0], 1u << (eo + k));
            s_ec[1][k] = lif(accB + b_ec[k], m_ec[1][k], em[1], 1u << (eo + k));
        }
#pragma unroll
        for (int k = 0; k < 2; ++k) {
            float accA = 0.f, accB = 0.f;
#pragma unroll
            for (int j = 0; j < 2; ++j) {
                const float4 w = sm.erI[k][j][role];
                accA = fmaf(xv[0][4*j+0], w.x, accA); accB = fmaf(xv[1][4*j+0], w.x, accB);
                accA = fmaf(xv[0][4*j+1], w.y, accA); accB = fmaf(xv[1][4*j+1], w.y, accB);
                accA = fmaf(xv[0][4*j+2], w.z, accA); accB = fmaf(xv[1][4*j+2], w.z, accB);
                accA = fmaf(xv[0][4*j+3], w.w, accA); accB = fmaf(xv[1][4*j+3], w.w, accB);
            }
            s_er[0][k] = lif(accA + b_er[k], m_er[0][k], em[0], 1u << (8 + eo + k));
            s_er[1][k] = lif(accB + b_er[k], m_er[1][k], em[1], 1u << (8 + eo + k));
        }
        em[0] = merge4(em[0]);
        em[1] = merge4(em[1]);

        // ---- shared layer: j-outer, unpack 4 bits at a time (ascending i) ----
        float acc6[2][6];
#pragma unroll
        for (int u = 0; u < 2; ++u)
#pragma unroll
            for (int k = 0; k < 6; ++k) acc6[u][k] = 0.f;
#pragma unroll
        for (int j = 0; j < 4; ++j) {
            float ea[4], eb[4];
#pragma unroll
            for (int c = 0; c < 4; ++c) { ea[c] = bit2f(em[0], 4*j+c); eb[c] = bit2f(em[1], 4*j+c); }
#pragma unroll
            for (int k = 0; k < 6; ++k) {
                const float4 w = sm.sI[k][j][role];
                acc6[0][k] = fmaf(ea[0], w.x, acc6[0][k]); acc6[1][k] = fmaf(eb[0], w.x, acc6[1][k]);
                acc6[0][k] = fmaf(ea[1], w.y, acc6[0][k]); acc6[1][k] = fmaf(eb[1], w.y, acc6[1][k]);
                acc6[0][k] = fmaf(ea[2], w.z, acc6[0][k]); acc6[1][k] = fmaf(eb[2], w.z, acc6[1][k]);
                acc6[0][k] = fmaf(ea[3], w.w, acc6[0][k]); acc6[1][k] = fmaf(eb[3], w.w, acc6[1][k]);
            }
        }
        float s_sh[2][6];
        unsigned shm[2] = {0u, 0u};
#pragma unroll
        for (int u = 0; u < 2; ++u)
#pragma unroll
            for (int k = 0; k < 6; ++k)
                s_sh[u][k] = lif(acc6[u][k] + b_sh[k], m_sh[u][k], shm[u], 1u << (so + k));
        shm[0] = merge4(shm[0]);
        shm[1] = merge4(shm[1]);

        // shin materialized (reused by ch and rh-tree)
        float shin[2][24];
#pragma unroll
        for (int u = 0; u < 2; ++u)
#pragma unroll
            for (int i = 0; i < 24; ++i) shin[u][i] = bit2f(shm[u], i);

        // ---- classification hidden: j-outer over 4 accs x 2 elem ----
        float acc4[2][4];
#pragma unroll
        for (int u = 0; u < 2; ++u)
#pragma unroll
            for (int k = 0; k < 4; ++k) acc4[u][k] = 0.f;
#pragma unroll
        for (int j = 0; j < 6; ++j) {
#pragma unroll
            for (int k = 0; k < 4; ++k) {
                const float4 w = sm.chI[k][j][role];
                acc4[0][k] = fmaf(shin[0][4*j+0], w.x, acc4[0][k]); acc4[1][k] = fmaf(shin[1][4*j+0], w.x, acc4[1][k]);
                acc4[0][k] = fmaf(shin[0][4*j+1], w.y, acc4[0][k]); acc4[1][k] = fmaf(shin[1][4*j+1], w.y, acc4[1][k]);
                acc4[0][k] = fmaf(shin[0][4*j+2], w.z, acc4[0][k]); acc4[1][k] = fmaf(shin[1][4*j+2], w.z, acc4[1][k]);
                acc4[0][k] = fmaf(shin[0][4*j+3], w.w, acc4[0][k]); acc4[1][k] = fmaf(shin[1][4*j+3], w.w, acc4[1][k]);
            }
        }
        float s_ch[2][4];
        unsigned cr[2] = {0u, 0u};   // ch bits 0..15, rh bits 16..31
#pragma unroll
        for (int u = 0; u < 2; ++u)
#pragma unroll
            for (int k = 0; k < 4; ++k)
                s_ch[u][k] = lif(acc4[u][k] + b_ch[k], m_ch[u][k], cr[u], 1u << (ho + k));

        // ---- regression hidden: butterfly tree per row (bit-exact) ----
        float s_rh[2][4];
#pragma unroll
        for (int k = 0; k < 4; ++k) {
            float w24[24];
#pragma unroll
            for (int j = 0; j < 6; ++j) {
                const float4 w = sm.rhI[k][j][role];
                w24[4*j+0] = w.x; w24[4*j+1] = w.y; w24[4*j+2] = w.z; w24[4*j+3] = w.w;
            }
#pragma unroll
            for (int u = 0; u < 2; ++u) {
                float p[24];
#pragma unroll
                for (int i = 0; i < 24; ++i) p[i] = shin[u][i] * w24[i];
#pragma unroll
                for (int i = 0; i < 8; ++i) p[i] = p[i] + p[i + 16];
#pragma unroll
                for (int i = 0; i < 8; ++i) p[i] = p[i] + p[i + 8];
#pragma unroll
                for (int i = 0; i < 4; ++i) p[i] = p[i] + p[i + 4];
#pragma unroll
                for (int i = 0; i < 2; ++i) p[i] = p[i] + p[i + 2];
                s_rh[u][k] = lif(p[0] + p[1] + b_rh[k], m_rh[u][k], cr[u], 1u << (16 + ho + k));
            }
        }
        cr[0] = merge4(cr[0]);
        cr[1] = merge4(cr[1]);

        // ---- output tail: roles 0-2 -> Wco over s_ch; role 3 -> Wro over s_rh ----
#pragma unroll
        for (int u = 0; u < 2; ++u) {
            const unsigned tm = isco ? (cr[u] & 0xFFFFu) : (cr[u] >> 16);
            float acc = 0.f;
#pragma unroll
            for (int j = 0; j < 4; ++j) {
                const float4 w = sm.tI[j][role];
                acc = fmaf(bit2f(tm, 4*j+0), w.x, acc);
                acc = fmaf(bit2f(tm, 4*j+1), w.y, acc);
                acc = fmaf(bit2f(tm, 4*j+2), w.z, acc);
                acc = fmaf(bit2f(tm, 4*j+3), w.w, acc);
            }
            lif_nom(acc + btail, m_tail[u]);
        }

        // ---- global stores ----
#pragma unroll
        for (int u = 0; u < 2; ++u) {
            const size_t r = rA + (u ? 8 : 0);
            if (isco) p_mco[r * 3 + role] = m_tail[u];
            else      p_mro[r] = m_tail[u];
            *(float4*)(p_sch + r * 16 + ho) = make_float4(s_ch[u][0], s_ch[u][1], s_ch[u][2], s_ch[u][3]);
            *(float4*)(p_srh + r * 16 + ho) = make_float4(s_rh[u][0], s_rh[u][1], s_rh[u][2], s_rh[u][3]);
            float2* q = (float2*)(p_ssh + r * 24 + so);
            q[0] = make_float2(s_sh[u][0], s_sh[u][1]);
            q[1] = make_float2(s_sh[u][2], s_sh[u][3]);
            q[2] = make_float2(s_sh[u][4], s_sh[u][5]);
            *(float2*)(p_sec + r * 8 + eo) = make_float2(s_ec[u][0], s_ec[u][1]);
            *(float2*)(p_ser + r * 8 + eo) = make_float2(s_er[u][0], s_er[u][1]);
        }
    }
}

extern "C" void kernel_launch(void* const* d_in, const int* in_sizes, int n_in,
                              void* d_out, int out_size)
{
    snn_kernel<<<128, 256>>>(
        (const float*)d_in[0],
        (const float*)d_in[1],  (const float*)d_in[2],
        (const float*)d_in[3],  (const float*)d_in[4],
        (const float*)d_in[5],  (const float*)d_in[6],
        (const float*)d_in[7],  (const float*)d_in[8],
        (const float*)d_in[9],  (const float*)d_in[10],
        (const float*)d_in[11], (const float*)d_in[12],
        (const float*)d_in[13], (const float*)d_in[14],
        (float*)d_out);
}

// round 16
// speedup vs baseline: 1.2849x; 1.2849x over previous
#include <cuda_runtime.h>

#define TT 100
#define BB 16384

// Interleaved weights: [k][j][role] -> the 4 roles of a warp hit 4 CONSECUTIVE
// float4s inside one 64B LDS.128 window -> conflict-free broadcast.
// sp: per-element spike buffer, row stride 76 floats -> conflict-free float4
// reads across the 8 subs of a warp (banks 12*e mod 32, spans disjoint).
// Row layout: ec[0:8) er[8:16) sh[16:40) ch[40:56) rh[56:72)
struct Smem {
    float4 ecI[2][2][4];
    float4 erI[2][2][4];
    float4 sI [6][4][4];
    float4 chI[4][6][4];
    float4 rhI[4][6][4];
    float4 tI [4][4];      // roles 0-2 -> Wco rows, role 3 -> Wro
    float  sp[128][76];
    float  bec[8], ber[8], bs[24], bch[16], bco[3], brh[16], bro[1];
};

// snntorch Leaky, reset='subtract', THR=1, BETA=0.9 — bit-exact vs reference.
__device__ __forceinline__ float lif(float cur, float& m) {
    float mold = m;
    m = fmaf(0.9f, m, cur);
    if (mold > 1.0f) m -= 1.0f;
    return (m > 1.0f) ? 1.0f : 0.0f;
}

__global__ void __launch_bounds__(256)
snn_kernel(const float* __restrict__ x,
           const float* __restrict__ We_c, const float* __restrict__ be_c,
           const float* __restrict__ We_r, const float* __restrict__ be_r,
           const float* __restrict__ Wsp,  const float* __restrict__ bsp,
           const float* __restrict__ Wchp, const float* __restrict__ bchp,
           const float* __restrict__ Wcop, const float* __restrict__ bcop,
           const float* __restrict__ Wrhp, const float* __restrict__ brhp,
           const float* __restrict__ Wrop, const float* __restrict__ brop,
           float* __restrict__ out)
{
    __shared__ __align__(16) Smem sm;
    const int tid = threadIdx.x;

    // ---- staging: permute weights into interleaved layout ----
    for (int idx = tid; idx < 64; idx += 256) {          // ecI / erI
        int c = idx & 3, role = (idx >> 2) & 3, j = (idx >> 4) & 1, k = idx >> 5;
        int col = 4 * j + c, row = 2 * role + k;
        ((float*)sm.ecI)[idx] = (col < 6) ? We_c[row * 6 + col] : 0.f;
        ((float*)sm.erI)[idx] = (col < 6) ? We_r[row * 6 + col] : 0.f;
    }
    for (int idx = tid; idx < 384; idx += 256) {         // sI
        int c = idx & 3, role = (idx >> 2) & 3, j = (idx >> 4) & 3, k = idx >> 6;
        ((float*)sm.sI)[idx] = Wsp[(6 * role + k) * 16 + 4 * j + c];
    }
    for (int idx = tid; idx < 384; idx += 256) {         // chI / rhI
        int c = idx & 3, role = (idx >> 2) & 3, jk = idx >> 4;
        int j = jk % 6, k = jk / 6, off = (4 * role + k) * 24 + 4 * j + c;
        ((float*)sm.chI)[idx] = Wchp[off];
        ((float*)sm.rhI)[idx] = Wrhp[off];
    }
    for (int idx = tid; idx < 64; idx += 256) {          // tI
        int c = idx & 3, role = (idx >> 2) & 3, j = idx >> 4;
        ((float*)sm.tI)[idx] = (role < 3) ? Wcop[role * 16 + 4 * j + c]
                                          : Wrop[4 * j + c];
    }
    if (tid < 8)  { sm.bec[tid] = be_c[tid]; sm.ber[tid] = be_r[tid]; }
    if (tid < 24) sm.bs[tid]  = bsp[tid];
    if (tid < 16) { sm.bch[tid] = bchp[tid]; sm.brh[tid] = brhp[tid]; }
    if (tid < 3)  sm.bco[tid] = bcop[tid];
    if (tid == 0) sm.bro[0] = brop[0];
    __syncthreads();

    // ---- 4-way role split, 2 elements per thread ----
    const int lane = tid & 31;
    const int warp = tid >> 5;           // 0..7
    const int role = lane >> 3;          // 0..3
    const int sub  = lane & 7;
    const int elemA = warp * 16 + sub;
    const int elemB = elemA + 8;
    const int eA = blockIdx.x * 128 + elemA;

    const int eo = role * 2;
    const int so = role * 6;
    const int ho = role * 4;

    float* const sbA = &sm.sp[elemA][0];
    float* const sbB = &sm.sp[elemB][0];

    // ---- loop-invariant hoists: biases + small weights into registers ----
    float b_ec[2], b_er[2], b_sh[6], b_ch[4], b_rh[4];
    float4 wec[2][2], wer[2][2], wt[4];
#pragma unroll
    for (int k = 0; k < 2; ++k) {
        b_ec[k] = sm.bec[eo + k]; b_er[k] = sm.ber[eo + k];
#pragma unroll
        for (int j = 0; j < 2; ++j) { wec[k][j] = sm.ecI[k][j][role]; wer[k][j] = sm.erI[k][j][role]; }
    }
#pragma unroll
    for (int k = 0; k < 6; ++k) b_sh[k] = sm.bs[so + k];
#pragma unroll
    for (int k = 0; k < 4; ++k) { b_ch[k] = sm.bch[ho + k]; b_rh[k] = sm.brh[ho + k]; }
#pragma unroll
    for (int j = 0; j < 4; ++j) wt[j] = sm.tI[j][role];
    const float btail = (role < 3) ? sm.bco[role] : sm.bro[0];
    const int toff = (role < 3) ? 40 : 56;

    // membranes, per element
    float m_ec[2][2], m_er[2][2], m_sh[2][6], m_ch[2][4], m_rh[2][4], m_tail[2];
#pragma unroll
    for (int u = 0; u < 2; ++u) {
#pragma unroll
        for (int i = 0; i < 2; ++i) { m_ec[u][i] = 0.f; m_er[u][i] = 0.f; }
#pragma unroll
        for (int i = 0; i < 6; ++i) m_sh[u][i] = 0.f;
#pragma unroll
        for (int i = 0; i < 4; ++i) { m_ch[u][i] = 0.f; m_rh[u][i] = 0.f; }
        m_tail[u] = 0.f;
    }

    const size_t TB = (size_t)TT * BB;
    float* const p_mco = out;
    float* const p_sch = out + TB * 3;
    float* const p_mro = out + TB * 19;
    float* const p_srh = out + TB * 20;
    float* const p_ssh = out + TB * 36;
    float* const p_sec = out + TB * 60;
    float* const p_ser = out + TB * 68;

    // ---- prologue: load x[0] ----
    float xn[2][6];
#pragma unroll
    for (int u = 0; u < 2; ++u) {
        const float2* xp = (const float2*)(x + ((size_t)eA + (u ? 8 : 0)) * 6);
        const float2 a0 = xp[0], a1 = xp[1], a2 = xp[2];
        xn[u][0] = a0.x; xn[u][1] = a0.y; xn[u][2] = a1.x;
        xn[u][3] = a1.y; xn[u][4] = a2.x; xn[u][5] = a2.y;
    }

#pragma unroll 1
    for (int t = 0; t < TT; ++t) {
        const size_t rA = (size_t)t * BB + eA;
        const size_t rB = rA + 8;

        float xv[2][8];
#pragma unroll
        for (int u = 0; u < 2; ++u) {
            xv[u][0] = xn[u][0]; xv[u][1] = xn[u][1]; xv[u][2] = xn[u][2];
            xv[u][3] = xn[u][3]; xv[u][4] = xn[u][4]; xv[u][5] = xn[u][5];
            xv[u][6] = 0.f;      xv[u][7] = 0.f;
        }

        // ---- encoders (register weights) ----
        float s_ec[2][2], s_er[2][2];
#pragma unroll
        for (int k = 0; k < 2; ++k) {
            float accA = 0.f, accB = 0.f;
#pragma unroll
            for (int j = 0; j < 2; ++j) {
                const float4 w = wec[k][j];
                accA = fmaf(xv[0][4*j+0], w.x, accA); accB = fmaf(xv[1][4*j+0], w.x, accB);
                accA = fmaf(xv[0][4*j+1], w.y, accA); accB = fmaf(xv[1][4*j+1], w.y, accB);
                accA = fmaf(xv[0][4*j+2], w.z, accA); accB = fmaf(xv[1][4*j+2], w.z, accB);
                accA = fmaf(xv[0][4*j+3], w.w, accA); accB = fmaf(xv[1][4*j+3], w.w, accB);
            }
            s_ec[0][k] = lif(accA + b_ec[k], m_ec[0][k]);
            s_ec[1][k] = lif(accB + b_ec[k], m_ec[1][k]);
        }
#pragma unroll
        for (int k = 0; k < 2; ++k) {
            float accA = 0.f, accB = 0.f;
#pragma unroll
            for (int j = 0; j < 2; ++j) {
                const float4 w = wer[k][j];
                accA = fmaf(xv[0][4*j+0], w.x, accA); accB = fmaf(xv[1][4*j+0], w.x, accB);
                accA = fmaf(xv[0][4*j+1], w.y, accA); accB = fmaf(xv[1][4*j+1], w.y, accB);
                accA = fmaf(xv[0][4*j+2], w.z, accA); accB = fmaf(xv[1][4*j+2], w.z, accB);
                accA = fmaf(xv[0][4*j+3], w.w, accA); accB = fmaf(xv[1][4*j+3], w.w, accB);
            }
            s_er[0][k] = lif(accA + b_er[k], m_er[0][k]);
            s_er[1][k] = lif(accB + b_er[k], m_er[1][k]);
        }
        *(float2*)(sbA + eo)     = make_float2(s_ec[0][0], s_ec[0][1]);
        *(float2*)(sbA + 8 + eo) = make_float2(s_er[0][0], s_er[0][1]);
        *(float2*)(sbB + eo)     = make_float2(s_ec[1][0], s_ec[1][1]);
        *(float2*)(sbB + 8 + eo) = make_float2(s_er[1][0], s_er[1][1]);
        __syncwarp();

        // ---- prefetch x[t+1]: latency overlaps all head compute below ----
        {
            const size_t tn = (t + 1 < TT) ? (size_t)(t + 1) : (size_t)t;
            const size_t rN = tn * BB + eA;
#pragma unroll
            for (int u = 0; u < 2; ++u) {
                const float2* xp = (const float2*)(x + (rN + (u ? 8 : 0)) * 6);
                const float2 a0 = xp[0], a1 = xp[1], a2 = xp[2];
                xn[u][0] = a0.x; xn[u][1] = a0.y; xn[u][2] = a1.x;
                xn[u][3] = a1.y; xn[u][4] = a2.x; xn[u][5] = a2.y;
            }
        }

        // ---- shared layer ----
        float ein[2][16];
#pragma unroll
        for (int u = 0; u < 2; ++u) {
            const float4* p4 = (const float4*)(u ? sbB : sbA);
#pragma unroll
            for (int j = 0; j < 4; ++j) {
                const float4 v = p4[j];
                ein[u][4*j+0] = v.x; ein[u][4*j+1] = v.y;
                ein[u][4*j+2] = v.z; ein[u][4*j+3] = v.w;
            }
        }
        float s_sh[2][6];
#pragma unroll
        for (int k = 0; k < 6; ++k) {
            float accA = 0.f, accB = 0.f;
#pragma unroll
            for (int j = 0; j < 4; ++j) {
                const float4 w = sm.sI[k][j][role];
                accA = fmaf(ein[0][4*j+0], w.x, accA); accB = fmaf(ein[1][4*j+0], w.x, accB);
                accA = fmaf(ein[0][4*j+1], w.y, accA); accB = fmaf(ein[1][4*j+1], w.y, accB);
                accA = fmaf(ein[0][4*j+2], w.z, accA); accB = fmaf(ein[1][4*j+2], w.z, accB);
                accA = fmaf(ein[0][4*j+3], w.w, accA); accB = fmaf(ein[1][4*j+3], w.w, accB);
            }
            s_sh[0][k] = lif(accA + b_sh[k], m_sh[0][k]);
            s_sh[1][k] = lif(accB + b_sh[k], m_sh[1][k]);
        }
#pragma unroll
        for (int u = 0; u < 2; ++u) {
            float* sb = u ? sbB : sbA;
            *(float2*)(sb + 16 + so)     = make_float2(s_sh[u][0], s_sh[u][1]);
            *(float2*)(sb + 16 + so + 2) = make_float2(s_sh[u][2], s_sh[u][3]);
            *(float2*)(sb + 16 + so + 4) = make_float2(s_sh[u][4], s_sh[u][5]);
        }
        __syncwarp();

        float shin[2][24];
#pragma unroll
        for (int u = 0; u < 2; ++u) {
            const float4* p4 = (const float4*)((u ? sbB : sbA) + 16);
#pragma unroll
            for (int j = 0; j < 6; ++j) {
                const float4 v = p4[j];
                shin[u][4*j+0] = v.x; shin[u][4*j+1] = v.y;
                shin[u][4*j+2] = v.z; shin[u][4*j+3] = v.w;
            }
        }

        // ---- classification hidden ----
        float s_ch[2][4];
#pragma unroll
        for (int k = 0; k < 4; ++k) {
            float accA = 0.f, accB = 0.f;
#pragma unroll
            for (int j = 0; j < 6; ++j) {
                const float4 w = sm.chI[k][j][role];
                accA = fmaf(shin[0][4*j+0], w.x, accA); accB = fmaf(shin[1][4*j+0], w.x, accB);
                accA = fmaf(shin[0][4*j+1], w.y, accA); accB = fmaf(shin[1][4*j+1], w.y, accB);
                accA = fmaf(shin[0][4*j+2], w.z, accA); accB = fmaf(shin[1][4*j+2], w.z, accB);
                accA = fmaf(shin[0][4*j+3], w.w, accA); accB = fmaf(shin[1][4*j+3], w.w, accB);
            }
            s_ch[0][k] = lif(accA + b_ch[k], m_ch[0][k]);
            s_ch[1][k] = lif(accB + b_ch[k], m_ch[1][k]);
        }

        // ---- regression hidden: butterfly tree per row (bit-exact) ----
        float s_rh[2][4];
#pragma unroll
        for (int k = 0; k < 4; ++k) {
            float w24[24];
#pragma unroll
            for (int j = 0; j < 6; ++j) {
                const float4 w = sm.rhI[k][j][role];
                w24[4*j+0] = w.x; w24[4*j+1] = w.y; w24[4*j+2] = w.z; w24[4*j+3] = w.w;
            }
#pragma unroll
            for (int u = 0; u < 2; ++u) {
                float p[24];
#pragma unroll
                for (int i = 0; i < 24; ++i) p[i] = shin[u][i] * w24[i];
#pragma unroll
                for (int i = 0; i < 8; ++i) p[i] = p[i] + p[i + 16];
#pragma unroll
                for (int i = 0; i < 8; ++i) p[i] = p[i] + p[i + 8];
#pragma unroll
                for (int i = 0; i < 4; ++i) p[i] = p[i] + p[i + 4];
#pragma unroll
                for (int i = 0; i < 2; ++i) p[i] = p[i] + p[i + 2];
                s_rh[u][k] = lif(p[0] + p[1] + b_rh[k], m_rh[u][k]);
            }
        }
#pragma unroll
        for (int u = 0; u < 2; ++u) {
            float* sb = u ? sbB : sbA;
            *(float4*)(sb + 40 + ho) = make_float4(s_ch[u][0], s_ch[u][1], s_ch[u][2], s_ch[u][3]);
            *(float4*)(sb + 56 + ho) = make_float4(s_rh[u][0], s_rh[u][1], s_rh[u][2], s_rh[u][3]);
        }
        __syncwarp();

        // ---- output tail (register weights) ----
#pragma unroll
        for (int u = 0; u < 2; ++u) {
            const float4* tin = (const float4*)((u ? sbB : sbA) + toff);
            float acc = 0.f;
#pragma unroll
            for (int j = 0; j < 4; ++j) {
                const float4 s = tin[j];
                const float4 w = wt[j];
                acc = fmaf(s.x, w.x, acc);
                acc = fmaf(s.y, w.y, acc);
                acc = fmaf(s.z, w.z, acc);
                acc = fmaf(s.w, w.w, acc);
            }
            lif(acc + btail, m_tail[u]);
        }

        // ---- global stores ----
#pragma unroll
        for (int u = 0; u < 2; ++u) {
            const size_t r = u ? rB : rA;
            if (role < 3) p_mco[r * 3 + role] = m_tail[u];
            else          p_mro[r] = m_tail[u];
            *(float4*)(p_sch + r * 16 + ho) = make_float4(s_ch[u][0], s_ch[u][1], s_ch[u][2], s_ch[u][3]);
            *(float4*)(p_srh + r * 16 + ho) = make_float4(s_rh[u][0], s_rh[u][1], s_rh[u][2], s_rh[u][3]);
            float2* q = (float2*)(p_ssh + r * 24 + so);
            q[0] = make_float2(s_sh[u][0], s_sh[u][1]);
            q[1] = make_float2(s_sh[u][2], s_sh[u][3]);
            q[2] = make_float2(s_sh[u][4], s_sh[u][5]);
            *(float2*)(p_sec + r * 8 + eo) = make_float2(s_ec[u][0], s_ec[u][1]);
            *(float2*)(p_ser + r * 8 + eo) = make_float2(s_er[u][0], s_er[u][1]);
        }
    }
}

extern "C" void kernel_launch(void* const* d_in, const int* in_sizes, int n_in,
                              void* d_out, int out_size)
{
    snn_kernel<<<128, 256>>>(
        (const float*)d_in[0],
        (const float*)d_in[1],  (const float*)d_in[2],
        (const float*)d_in[3],  (const float*)d_in[4],
        (const float*)d_in[5],  (const float*)d_in[6],
        (const float*)d_in[7],  (const float*)d_in[8],
        (const float*)d_in[9],  (const float*)d_in[10],
        (const float*)d_in[11], (const float*)d_in[12],
        (const float*)d_in[13], (const float*)d_in[14],
        (float*)d_out);
}

// round 17
// speedup vs baseline: 1.3576x; 1.0566x over previous
#include <cuda_runtime.h>

#define TT 100
#define BB 16384

// Interleaved weights: [k][j][role] -> the 4 roles of a warp hit 4 CONSECUTIVE
// float4s inside one 64B LDS.128 window -> conflict-free broadcast.
// sp: per-element spike buffer, row stride 76 floats -> conflict-free float4
// reads across the 8 subs of a warp (banks 12*e mod 32, spans disjoint).
// Row layout: ec[0:8) er[8:16) sh[16:40) ch[40:56) rh[56:72)
struct Smem {
    float4 ecI[2][2][4];
    float4 erI[2][2][4];
    float4 sI [6][4][4];
    float4 chI[4][6][4];
    float4 rhI[4][6][4];
    float4 tI [4][4];      // roles 0-2 -> Wco rows, role 3 -> Wro
    float  sp[112][76];    // 7 warps x 16 elements
    float  bec[8], ber[8], bs[24], bch[16], bco[3], brh[16], bro[1];
};

// snntorch Leaky, reset='subtract', THR=1, BETA=0.9 — bit-exact vs reference.
__device__ __forceinline__ float lif(float cur, float& m) {
    float mold = m;
    m = fmaf(0.9f, m, cur);
    if (mold > 1.0f) m -= 1.0f;
    return (m > 1.0f) ? 1.0f : 0.0f;
}

#define NTHR 224   // 7 warps; 148 blocks x 7 = 1036 warp slots >= 1024 tiles

__global__ void __launch_bounds__(NTHR)
snn_kernel(const float* __restrict__ x,
           const float* __restrict__ We_c, const float* __restrict__ be_c,
           const float* __restrict__ We_r, const float* __restrict__ be_r,
           const float* __restrict__ Wsp,  const float* __restrict__ bsp,
           const float* __restrict__ Wchp, const float* __restrict__ bchp,
           const float* __restrict__ Wcop, const float* __restrict__ bcop,
           const float* __restrict__ Wrhp, const float* __restrict__ brhp,
           const float* __restrict__ Wrop, const float* __restrict__ brop,
           float* __restrict__ out)
{
    __shared__ __align__(16) Smem sm;
    const int tid = threadIdx.x;

    // ---- staging: permute weights into interleaved layout ----
    for (int idx = tid; idx < 64; idx += NTHR) {          // ecI / erI
        int c = idx & 3, role = (idx >> 2) & 3, j = (idx >> 4) & 1, k = idx >> 5;
        int col = 4 * j + c, row = 2 * role + k;
        ((float*)sm.ecI)[idx] = (col < 6) ? We_c[row * 6 + col] : 0.f;
        ((float*)sm.erI)[idx] = (col < 6) ? We_r[row * 6 + col] : 0.f;
    }
    for (int idx = tid; idx < 384; idx += NTHR) {         // sI
        int c = idx & 3, role = (idx >> 2) & 3, j = (idx >> 4) & 3, k = idx >> 6;
        ((float*)sm.sI)[idx] = Wsp[(6 * role + k) * 16 + 4 * j + c];
    }
    for (int idx = tid; idx < 384; idx += NTHR) {         // chI / rhI
        int c = idx & 3, role = (idx >> 2) & 3, jk = idx >> 4;
        int j = jk % 6, k = jk / 6, off = (4 * role + k) * 24 + 4 * j + c;
        ((float*)sm.chI)[idx] = Wchp[off];
        ((float*)sm.rhI)[idx] = Wrhp[off];
    }
    for (int idx = tid; idx < 64; idx += NTHR) {          // tI
        int c = idx & 3, role = (idx >> 2) & 3, j = idx >> 4;
        ((float*)sm.tI)[idx] = (role < 3) ? Wcop[role * 16 + 4 * j + c]
                                          : Wrop[4 * j + c];
    }
    if (tid < 8)  { sm.bec[tid] = be_c[tid]; sm.ber[tid] = be_r[tid]; }
    if (tid < 24) sm.bs[tid]  = bsp[tid];
    if (tid < 16) { sm.bch[tid] = bchp[tid]; sm.brh[tid] = brhp[tid]; }
    if (tid < 3)  sm.bco[tid] = bcop[tid];
    if (tid == 0) sm.bro[0] = brop[0];
    __syncthreads();

    // ---- warp-slot -> 16-element tile; 4-way role split, 2 elem/thread ----
    const int lane = tid & 31;
    const int warp = tid >> 5;                 // 0..6
    const int slot = blockIdx.x * 7 + warp;    // global tile id
    if (slot >= 1024) return;                  // 12 idle warps; no block syncs follow

    const int role = lane >> 3;                // 0..3
    const int sub  = lane & 7;
    const int elemA = warp * 16 + sub;         // block-local spike-buffer row
    const int elemB = elemA + 8;
    const int eA = slot * 16 + sub;            // global element (eB = eA + 8)

    const int eo = role * 2;
    const int so = role * 6;
    const int ho = role * 4;

    float* const sbA = &sm.sp[elemA][0];
    float* const sbB = &sm.sp[elemB][0];

    // ---- loop-invariant hoists: biases + small weights into registers ----
    float b_ec[2], b_er[2], b_sh[6], b_ch[4], b_rh[4];
    float4 wec[2][2], wer[2][2], wt[4];
#pragma unroll
    for (int k = 0; k < 2; ++k) {
        b_ec[k] = sm.bec[eo + k]; b_er[k] = sm.ber[eo + k];
#pragma unroll
        for (int j = 0; j < 2; ++j) { wec[k][j] = sm.ecI[k][j][role]; wer[k][j] = sm.erI[k][j][role]; }
    }
#pragma unroll
    for (int k = 0; k < 6; ++k) b_sh[k] = sm.bs[so + k];
#pragma unroll
    for (int k = 0; k < 4; ++k) { b_ch[k] = sm.bch[ho + k]; b_rh[k] = sm.brh[ho + k]; }
#pragma unroll
    for (int j = 0; j < 4; ++j) wt[j] = sm.tI[j][role];
    const float btail = (role < 3) ? sm.bco[role] : sm.bro[0];
    const int toff = (role < 3) ? 40 : 56;

    // membranes, per element
    float m_ec[2][2], m_er[2][2], m_sh[2][6], m_ch[2][4], m_rh[2][4], m_tail[2];
#pragma unroll
    for (int u = 0; u < 2; ++u) {
#pragma unroll
        for (int i = 0; i < 2; ++i) { m_ec[u][i] = 0.f; m_er[u][i] = 0.f; }
#pragma unroll
        for (int i = 0; i < 6; ++i) m_sh[u][i] = 0.f;
#pragma unroll
        for (int i = 0; i < 4; ++i) { m_ch[u][i] = 0.f; m_rh[u][i] = 0.f; }
        m_tail[u] = 0.f;
    }

    const size_t TB = (size_t)TT * BB;
    float* const p_mco = out;
    float* const p_sch = out + TB * 3;
    float* const p_mro = out + TB * 19;
    float* const p_srh = out + TB * 20;
    float* const p_ssh = out + TB * 36;
    float* const p_sec = out + TB * 60;
    float* const p_ser = out + TB * 68;

    // ---- prologue: load x[0] ----
    float xn[2][6];
#pragma unroll
    for (int u = 0; u < 2; ++u) {
        const float2* xp = (const float2*)(x + ((size_t)eA + (u ? 8 : 0)) * 6);
        const float2 a0 = xp[0], a1 = xp[1], a2 = xp[2];
        xn[u][0] = a0.x; xn[u][1] = a0.y; xn[u][2] = a1.x;
        xn[u][3] = a1.y; xn[u][4] = a2.x; xn[u][5] = a2.y;
    }

#pragma unroll 1
    for (int t = 0; t < TT; ++t) {
        const size_t rA = (size_t)t * BB + eA;
        const size_t rB = rA + 8;

        float xv[2][8];
#pragma unroll
        for (int u = 0; u < 2; ++u) {
            xv[u][0] = xn[u][0]; xv[u][1] = xn[u][1]; xv[u][2] = xn[u][2];
            xv[u][3] = xn[u][3]; xv[u][4] = xn[u][4]; xv[u][5] = xn[u][5];
            xv[u][6] = 0.f;      xv[u][7] = 0.f;
        }

        // ---- encoders (register weights) ----
        float s_ec[2][2], s_er[2][2];
#pragma unroll
        for (int k = 0; k < 2; ++k) {
            float accA = 0.f, accB = 0.f;
#pragma unroll
            for (int j = 0; j < 2; ++j) {
                const float4 w = wec[k][j];
                accA = fmaf(xv[0][4*j+0], w.x, accA); accB = fmaf(xv[1][4*j+0], w.x, accB);
                accA = fmaf(xv[0][4*j+1], w.y, accA); accB = fmaf(xv[1][4*j+1], w.y, accB);
                accA = fmaf(xv[0][4*j+2], w.z, accA); accB = fmaf(xv[1][4*j+2], w.z, accB);
                accA = fmaf(xv[0][4*j+3], w.w, accA); accB = fmaf(xv[1][4*j+3], w.w, accB);
            }
            s_ec[0][k] = lif(accA + b_ec[k], m_ec[0][k]);
            s_ec[1][k] = lif(accB + b_ec[k], m_ec[1][k]);
        }
#pragma unroll
        for (int k = 0; k < 2; ++k) {
            float accA = 0.f, accB = 0.f;
#pragma unroll
            for (int j = 0; j < 2; ++j) {
                const float4 w = wer[k][j];
                accA = fmaf(xv[0][4*j+0], w.x, accA); accB = fmaf(xv[1][4*j+0], w.x, accB);
                accA = fmaf(xv[0][4*j+1], w.y, accA); accB = fmaf(xv[1][4*j+1], w.y, accB);
                accA = fmaf(xv[0][4*j+2], w.z, accA); accB = fmaf(xv[1][4*j+2], w.z, accB);
                accA = fmaf(xv[0][4*j+3], w.w, accA); accB = fmaf(xv[1][4*j+3], w.w, accB);
            }
            s_er[0][k] = lif(accA + b_er[k], m_er[0][k]);
            s_er[1][k] = lif(accB + b_er[k], m_er[1][k]);
        }
        *(float2*)(sbA + eo)     = make_float2(s_ec[0][0], s_ec[0][1]);
        *(float2*)(sbA + 8 + eo) = make_float2(s_er[0][0], s_er[0][1]);
        *(float2*)(sbB + eo)     = make_float2(s_ec[1][0], s_ec[1][1]);
        *(float2*)(sbB + 8 + eo) = make_float2(s_er[1][0], s_er[1][1]);
        __syncwarp();

        // ---- prefetch x[t+1]: latency overlaps all head compute below ----
        {
            const size_t tn = (t + 1 < TT) ? (size_t)(t + 1) : (size_t)t;
            const size_t rN = tn * BB + eA;
#pragma unroll
            for (int u = 0; u < 2; ++u) {
                const float2* xp = (const float2*)(x + (rN + (u ? 8 : 0)) * 6);
                const float2 a0 = xp[0], a1 = xp[1], a2 = xp[2];
                xn[u][0] = a0.x; xn[u][1] = a0.y; xn[u][2] = a1.x;
                xn[u][3] = a1.y; xn[u][4] = a2.x; xn[u][5] = a2.y;
            }
        }

        // ---- shared layer ----
        float ein[2][16];
#pragma unroll
        for (int u = 0; u < 2; ++u) {
            const float4* p4 = (const float4*)(u ? sbB : sbA);
#pragma unroll
            for (int j = 0; j < 4; ++j) {
                const float4 v = p4[j];
                ein[u][4*j+0] = v.x; ein[u][4*j+1] = v.y;
                ein[u][4*j+2] = v.z; ein[u][4*j+3] = v.w;
            }
        }
        float s_sh[2][6];
#pragma unroll
        for (int k = 0; k < 6; ++k) {
            float accA = 0.f, accB = 0.f;
#pragma unroll
            for (int j = 0; j < 4; ++j) {
                const float4 w = sm.sI[k][j][role];
                accA = fmaf(ein[0][4*j+0], w.x, accA); accB = fmaf(ein[1][4*j+0], w.x, accB);
                accA = fmaf(ein[0][4*j+1], w.y, accA); accB = fmaf(ein[1][4*j+1], w.y, accB);
                accA = fmaf(ein[0][4*j+2], w.z, accA); accB = fmaf(ein[1][4*j+2], w.z, accB);
                accA = fmaf(ein[0][4*j+3], w.w, accA); accB = fmaf(ein[1][4*j+3], w.w, accB);
            }
            s_sh[0][k] = lif(accA + b_sh[k], m_sh[0][k]);
            s_sh[1][k] = lif(accB + b_sh[k], m_sh[1][k]);
        }
#pragma unroll
        for (int u = 0; u < 2; ++u) {
            float* sb = u ? sbB : sbA;
            *(float2*)(sb + 16 + so)     = make_float2(s_sh[u][0], s_sh[u][1]);
            *(float2*)(sb + 16 + so + 2) = make_float2(s_sh[u][2], s_sh[u][3]);
            *(float2*)(sb + 16 + so + 4) = make_float2(s_sh[u][4], s_sh[u][5]);
        }
        __syncwarp();

        float shin[2][24];
#pragma unroll
        for (int u = 0; u < 2; ++u) {
            const float4* p4 = (const float4*)((u ? sbB : sbA) + 16);
#pragma unroll
            for (int j = 0; j < 6; ++j) {
                const float4 v = p4[j];
                shin[u][4*j+0] = v.x; shin[u][4*j+1] = v.y;
                shin[u][4*j+2] = v.z; shin[u][4*j+3] = v.w;
            }
        }

        // ---- classification hidden ----
        float s_ch[2][4];
#pragma unroll
        for (int k = 0; k < 4; ++k) {
            float accA = 0.f, accB = 0.f;
#pragma unroll
            for (int j = 0; j < 6; ++j) {
                const float4 w = sm.chI[k][j][role];
                accA = fmaf(shin[0][4*j+0], w.x, accA); accB = fmaf(shin[1][4*j+0], w.x, accB);
                accA = fmaf(shin[0][4*j+1], w.y, accA); accB = fmaf(shin[1][4*j+1], w.y, accB);
                accA = fmaf(shin[0][4*j+2], w.z, accA); accB = fmaf(shin[1][4*j+2], w.z, accB);
                accA = fmaf(shin[0][4*j+3], w.w, accA); accB = fmaf(shin[1][4*j+3], w.w, accB);
            }
            s_ch[0][k] = lif(accA + b_ch[k], m_ch[0][k]);
            s_ch[1][k] = lif(accB + b_ch[k], m_ch[1][k]);
        }

        // ---- regression hidden: butterfly tree per row (bit-exact) ----
        float s_rh[2][4];
#pragma unroll
        for (int k = 0; k < 4; ++k) {
            float w24[24];
#pragma unroll
            for (int j = 0; j < 6; ++j) {
                const float4 w = sm.rhI[k][j][role];
                w24[4*j+0] = w.x; w24[4*j+1] = w.y; w24[4*j+2] = w.z; w24[4*j+3] = w.w;
            }
#pragma unroll
            for (int u = 0; u < 2; ++u) {
                float p[24];
#pragma unroll
                for (int i = 0; i < 24; ++i) p[i] = shin[u][i] * w24[i];
#pragma unroll
                for (int i = 0; i < 8; ++i) p[i] = p[i] + p[i + 16];
#pragma unroll
                for (int i = 0; i < 8; ++i) p[i] = p[i] + p[i + 8];
#pragma unroll
                for (int i = 0; i < 4; ++i) p[i] = p[i] + p[i + 4];
#pragma unroll
                for (int i = 0; i < 2; ++i) p[i] = p[i] + p[i + 2];
                s_rh[u][k] = lif(p[0] + p[1] + b_rh[k], m_rh[u][k]);
            }
        }
#pragma unroll
        for (int u = 0; u < 2; ++u) {
            float* sb = u ? sbB : sbA;
            *(float4*)(sb + 40 + ho) = make_float4(s_ch[u][0], s_ch[u][1], s_ch[u][2], s_ch[u][3]);
            *(float4*)(sb + 56 + ho) = make_float4(s_rh[u][0], s_rh[u][1], s_rh[u][2], s_rh[u][3]);
        }
        __syncwarp();

        // ---- output tail (register weights) ----
#pragma unroll
        for (int u = 0; u < 2; ++u) {
            const float4* tin = (const float4*)((u ? sbB : sbA) + toff);
            float acc = 0.f;
#pragma unroll
            for (int j = 0; j < 4; ++j) {
                const float4 s = tin[j];
                const float4 w = wt[j];
                acc = fmaf(s.x, w.x, acc);
                acc = fmaf(s.y, w.y, acc);
                acc = fmaf(s.z, w.z, acc);
                acc = fmaf(s.w, w.w, acc);
            }
            lif(acc + btail, m_tail[u]);
        }

        // ---- global stores ----
#pragma unroll
        for (int u = 0; u < 2; ++u) {
            const size_t r = u ? rB : rA;
            if (role < 3) p_mco[r * 3 + role] = m_tail[u];
            else          p_mro[r] = m_tail[u];
            *(float4*)(p_sch + r * 16 + ho) = make_float4(s_ch[u][0], s_ch[u][1], s_ch[u][2], s_ch[u][3]);
            *(float4*)(p_srh + r * 16 + ho) = make_float4(s_rh[u][0], s_rh[u][1], s_rh[u][2], s_rh[u][3]);
            float2* q = (float2*)(p_ssh + r * 24 + so);
            q[0] = make_float2(s_sh[u][0], s_sh[u][1]);
            q[1] = make_float2(s_sh[u][2], s_sh[u][3]);
            q[2] = make_float2(s_sh[u][4], s_sh[u][5]);
            *(float2*)(p_sec + r * 8 + eo) = make_float2(s_ec[u][0], s_ec[u][1]);
            *(float2*)(p_ser + r * 8 + eo) = make_float2(s_er[u][0], s_er[u][1]);
        }
    }
}

extern "C" void kernel_launch(void* const* d_in, const int* in_sizes, int n_in,
                              void* d_out, int out_size)
{
    snn_kernel<<<148, NTHR>>>(
        (const float*)d_in[0],
        (const float*)d_in[1],  (const float*)d_in[2],
        (const float*)d_in[3],  (const float*)d_in[4],
        (const float*)d_in[5],  (const float*)d_in[6],
        (const float*)d_in[7],  (const float*)d_in[8],
        (const float*)d_in[9],  (const float*)d_in[10],
        (const float*)d_in[11], (const float*)d_in[12],
        (const float*)d_in[13], (const float*)d_in[14],
        (float*)d_out);
}